// round 4
// baseline (speedup 1.0000x reference)
#include <cuda_runtime.h>
#include <cuda_bf16.h>

// inputs:  [B=32, 56, 56, C=256] fp32 ; routing: [32, 4] fp32
// out[b,h,w,j] = inputs[b,h,w, argmax(routing[b])*64 + j]  -> [32,56,56,64]
// Latency-bound per-pixel 256B gather (input is L2-resident; DRAM sees only
// stores). Lever: MLP=8 front-batched LDG.128 + near-single-wave grid.

namespace {
constexpr int B       = 32;
constexpr int HW      = 56 * 56;      // 3136
constexpr int ROUTES  = 4;
constexpr int V       = 16;           // float4 per output pixel (64 floats)
constexpr int CV      = 64;           // float4 per input pixel (256 floats)
constexpr int THREADS = 128;          // 4 warps/block
constexpr int PER_TH  = 8;            // float4 per thread (MLP=8)
constexpr int PER_BLK = THREADS * PER_TH;                 // 1024
constexpr long long TOTAL_V4 = (long long)B * HW * V;     // 1,605,632
constexpr int BLOCKS  = (int)(TOTAL_V4 / PER_BLK);        // 1568 (exact)
constexpr int BLOCKS_PER_BATCH = BLOCKS / B;              // 49   (exact)
}

__global__ __launch_bounds__(THREADS)
void routing_gather_kernel(const float4* __restrict__ in4,
                           const float*  __restrict__ routing,
                           float4* __restrict__ out4)
{
    // Block covers PER_BLK consecutive output float4s, all within one batch.
    const int b = blockIdx.x / BLOCKS_PER_BATCH;

    // argmax over 4 logits; uniform address across block -> L1 broadcast.
    const float* r = routing + b * ROUTES;
    float best = r[0];
    int route = 0;
#pragma unroll
    for (int k = 1; k < ROUTES; ++k) {
        float v = r[k];
        if (v > best) { best = v; route = k; }
    }
    const int rbase = route * V;

    // Warp-coalesced layout: warp owns 256 consecutive f4, lane-stride 32.
    const int base = blockIdx.x * PER_BLK
                   + (threadIdx.x >> 5) * (32 * PER_TH)
                   + (threadIdx.x & 31);

    // 8 independent coalesced LDG.128, front-batched (MLP_p1 = 8).
    float4 v[PER_TH];
#pragma unroll
    for (int k = 0; k < PER_TH; ++k) {
        int idx = base + k * 32;          // global output float4 index
        int t   = idx >> 4;               // pixel index (b*HW + pix)
        int j   = idx & (V - 1);          // float4 within pixel
        v[k] = __ldg(&in4[(long long)t * CV + rbase + j]);
    }
    // Evict-first stores: don't let output traffic evict the L2-resident input.
#pragma unroll
    for (int k = 0; k < PER_TH; ++k) {
        __stcs(&out4[base + k * 32], v[k]);
    }
}

extern "C" void kernel_launch(void* const* d_in, const int* in_sizes, int n_in,
                              void* d_out, int out_size)
{
    const float4* in4     = (const float4*)d_in[0];
    const float*  routing = (const float*)d_in[1];
    float4*       out4    = (float4*)d_out;

    routing_gather_kernel<<<BLOCKS, THREADS>>>(in4, routing, out4);
}

// round 6
// speedup vs baseline: 1.0269x; 1.0269x over previous
#include <cuda_runtime.h>
#include <cuda_bf16.h>

// inputs:  [B=32, 56, 56, C=256] fp32 ; routing: [32, 4] fp32
// out[b,h,w,j] = inputs[b,h,w, argmax(routing[b])*64 + j]  -> [32,56,56,64]
//
// Latency/occupancy-bound gather (reads are L2 hits; DRAM sees only stores).
// R5: exactly-one-wave grid (8 blocks/SM x 148 SMs), 64 warps/SM resident,
// smem route LUT (no per-element routing-load dependency), L2-only loads.

namespace {
constexpr int B       = 32;
constexpr int HW      = 56 * 56;      // 3136 pixels per batch
constexpr int ROUTES  = 4;
constexpr int V       = 16;           // float4 per output pixel
constexpr int CV      = 64;           // float4 per input pixel
constexpr int THREADS = 256;
constexpr int BLOCKS  = 8 * 148;      // 1184: one full wave at 8 blocks/SM
constexpr int STRIDE  = BLOCKS * THREADS;                 // 303,104
constexpr long long TOTAL_V4 = (long long)B * HW * V;     // 1,605,632
constexpr int FULL_ITERS = (int)(TOTAL_V4 / STRIDE);      // 5
constexpr int TAIL = (int)(TOTAL_V4 - (long long)FULL_ITERS * STRIDE); // 90,112
}

__global__ __launch_bounds__(THREADS)
void routing_gather_kernel(const float4* __restrict__ in4,
                           const float*  __restrict__ routing,
                           float4* __restrict__ out4)
{
    // Per-block route LUT: rbase[b] = argmax(routing[b]) * V.
    __shared__ int rbase[B];
    if (threadIdx.x < B) {
        const float* r = routing + threadIdx.x * ROUTES;
        float best = r[0];
        int route = 0;
#pragma unroll
        for (int k = 1; k < ROUTES; ++k) {
            float v = r[k];
            if (v > best) { best = v; route = k; }  // strict > = first-max tie
        }
        rbase[threadIdx.x] = route * V;
    }
    __syncthreads();

    const int base = blockIdx.x * THREADS + threadIdx.x;

    // 5 unconditional elements + 1 predicated tail; loads front-batched.
    float4 v[FULL_ITERS + 1];
#pragma unroll
    for (int k = 0; k < FULL_ITERS; ++k) {
        int idx = base + k * STRIDE;      // output float4 index
        int t   = idx >> 4;               // pixel index (b*HW + pix)
        int j   = idx & (V - 1);
        int b   = t / HW;                 // const-divisor -> mulhi
        v[k] = __ldcg(&in4[(long long)t * CV + rbase[b] + j]);
    }
    const bool tail = base < TAIL;
    if (tail) {
        int idx = base + FULL_ITERS * STRIDE;
        int t   = idx >> 4;
        int j   = idx & (V - 1);
        int b   = t / HW;
        v[FULL_ITERS] = __ldcg(&in4[(long long)t * CV + rbase[b] + j]);
    }

#pragma unroll
    for (int k = 0; k < FULL_ITERS; ++k) {
        out4[base + k * STRIDE] = v[k];
    }
    if (tail) {
        out4[base + FULL_ITERS * STRIDE] = v[FULL_ITERS];
    }
}

extern "C" void kernel_launch(void* const* d_in, const int* in_sizes, int n_in,
                              void* d_out, int out_size)
{
    const float4* in4     = (const float4*)d_in[0];
    const float*  routing = (const float*)d_in[1];
    float4*       out4    = (float4*)d_out;

    routing_gather_kernel<<<BLOCKS, THREADS>>>(in4, routing, out4);
}